// round 4
// baseline (speedup 1.0000x reference)
#include <cuda_runtime.h>
#include <cstdint>

// MaxUnpooling2D: B=16, H=128, W=128, C=64, S=2 -> out (16, 256, 256, 64)
// Each (h,w,c) scatters into its OWN 2x2 window at channel c (unique owner
// per output cell) -> one-pass window write, no atomics, no memset.
//
// R4: single-wave persistent grid (1024 blocks x 256 thr, exactly 16 iters
// per thread, no bounds checks) + 1-deep prefetch pipeline. Removes wave
// transitions of the 16384-block launch while keeping regs low (~30).

static constexpr int W  = 128;
static constexpr int C  = 64;
static constexpr int Wo = 256;        // W*2
static constexpr int N4 = (16 * 128 * 128 * 64) / 4;  // 2^22 float4 elements
static constexpr int BLOCKS  = 1024;
static constexpr int THREADS = 256;
static constexpr int STRIDE  = BLOCKS * THREADS;      // 2^18
static constexpr int ITERS   = N4 / STRIDE;           // 16

__device__ __forceinline__ void process_one(int idx, float4 u, int4 m,
                                            float* __restrict__ out)
{
    // idx layout: [ b*H + h ][ w ][ c4 ], c4 in [0,16)
    int c4 = idx & 15;
    int w  = (idx >> 4) & (W - 1);
    int hb = idx >> 11;               // b*H + h

    float4 v0 = {0.f, 0.f, 0.f, 0.f};
    float4 v1 = v0, v2 = v0, v3 = v0;

    // t = mask >> 6 (= y*Wo + x); dx = t & 1; dy = (t >> 8) & 1; q = dy*2+dx
#define PLACE(comp)                                                   \
    {                                                                 \
        int t = m.comp >> 6;                                          \
        int q = ((t >> 7) & 2) | (t & 1);                             \
        v0.comp = (q == 0) ? u.comp : 0.f;                            \
        v1.comp = (q == 1) ? u.comp : 0.f;                            \
        v2.comp = (q == 2) ? u.comp : 0.f;                            \
        v3.comp = (q == 3) ? u.comp : 0.f;                            \
    }
    PLACE(x) PLACE(y) PLACE(z) PLACE(w)
#undef PLACE

    // output base: (2*hb*Wo + 2*w) * C + c4*4
    int base = ((hb * Wo + w) << 1) * C + (c4 << 2);

    __stcs(reinterpret_cast<float4*>(out + base),              v0); // (2h,  2w  )
    __stcs(reinterpret_cast<float4*>(out + base + C),          v1); // (2h,  2w+1)
    __stcs(reinterpret_cast<float4*>(out + base + Wo * C),     v2); // (2h+1,2w  )
    __stcs(reinterpret_cast<float4*>(out + base + Wo * C + C), v3); // (2h+1,2w+1)
}

__global__ __launch_bounds__(THREADS) void unpool_kernel(
    const float4* __restrict__ upd4,
    const int4* __restrict__ msk4,
    float* __restrict__ out)
{
    int i = blockIdx.x * THREADS + threadIdx.x;

    // 1-deep prefetch pipeline: loads for iter j+1 in flight while storing j.
    float4 u = __ldcs(&upd4[i]);
    int4   m = __ldcs(&msk4[i]);

#pragma unroll 1
    for (int j = 0; j < ITERS - 1; j++) {
        int next = i + STRIDE;
        float4 un = __ldcs(&upd4[next]);
        int4   mn = __ldcs(&msk4[next]);
        process_one(i, u, m, out);
        i = next; u = un; m = mn;
    }
    process_one(i, u, m, out);
}

extern "C" void kernel_launch(void* const* d_in, const int* in_sizes, int n_in,
                              void* d_out, int out_size)
{
    const float4* upd4 = (const float4*)d_in[0];
    const int4*   msk4 = (const int4*)d_in[1];
    float*        out  = (float*)d_out;

    unpool_kernel<<<BLOCKS, THREADS>>>(upd4, msk4, out);
}

// round 5
// speedup vs baseline: 1.0026x; 1.0026x over previous
#include <cuda_runtime.h>
#include <cstdint>

// MaxUnpooling2D: B=16, H=128, W=128, C=64, S=2 -> out (16, 256, 256, 64)
// Each (h,w,c) scatters into its OWN 2x2 window at channel c (unique owner
// per output cell) -> one-pass window write, no atomics, no memset.
//
// R4: single-wave persistent grid (1024 blocks x 256 thr, exactly 16 iters
// per thread, no bounds checks) + 1-deep prefetch pipeline. Removes wave
// transitions of the 16384-block launch while keeping regs low (~30).

static constexpr int W  = 128;
static constexpr int C  = 64;
static constexpr int Wo = 256;        // W*2
static constexpr int N4 = (16 * 128 * 128 * 64) / 4;  // 2^22 float4 elements
static constexpr int BLOCKS  = 1024;
static constexpr int THREADS = 256;
static constexpr int STRIDE  = BLOCKS * THREADS;      // 2^18
static constexpr int ITERS   = N4 / STRIDE;           // 16

__device__ __forceinline__ void process_one(int idx, float4 u, int4 m,
                                            float* __restrict__ out)
{
    // idx layout: [ b*H + h ][ w ][ c4 ], c4 in [0,16)
    int c4 = idx & 15;
    int w  = (idx >> 4) & (W - 1);
    int hb = idx >> 11;               // b*H + h

    float4 v0 = {0.f, 0.f, 0.f, 0.f};
    float4 v1 = v0, v2 = v0, v3 = v0;

    // t = mask >> 6 (= y*Wo + x); dx = t & 1; dy = (t >> 8) & 1; q = dy*2+dx
#define PLACE(comp)                                                   \
    {                                                                 \
        int t = m.comp >> 6;                                          \
        int q = ((t >> 7) & 2) | (t & 1);                             \
        v0.comp = (q == 0) ? u.comp : 0.f;                            \
        v1.comp = (q == 1) ? u.comp : 0.f;                            \
        v2.comp = (q == 2) ? u.comp : 0.f;                            \
        v3.comp = (q == 3) ? u.comp : 0.f;                            \
    }
    PLACE(x) PLACE(y) PLACE(z) PLACE(w)
#undef PLACE

    // output base: (2*hb*Wo + 2*w) * C + c4*4
    int base = ((hb * Wo + w) << 1) * C + (c4 << 2);

    __stcs(reinterpret_cast<float4*>(out + base),              v0); // (2h,  2w  )
    __stcs(reinterpret_cast<float4*>(out + base + C),          v1); // (2h,  2w+1)
    __stcs(reinterpret_cast<float4*>(out + base + Wo * C),     v2); // (2h+1,2w  )
    __stcs(reinterpret_cast<float4*>(out + base + Wo * C + C), v3); // (2h+1,2w+1)
}

__global__ __launch_bounds__(THREADS) void unpool_kernel(
    const float4* __restrict__ upd4,
    const int4* __restrict__ msk4,
    float* __restrict__ out)
{
    int i = blockIdx.x * THREADS + threadIdx.x;

    // 1-deep prefetch pipeline: loads for iter j+1 in flight while storing j.
    float4 u = __ldcs(&upd4[i]);
    int4   m = __ldcs(&msk4[i]);

#pragma unroll 1
    for (int j = 0; j < ITERS - 1; j++) {
        int next = i + STRIDE;
        float4 un = __ldcs(&upd4[next]);
        int4   mn = __ldcs(&msk4[next]);
        process_one(i, u, m, out);
        i = next; u = un; m = mn;
    }
    process_one(i, u, m, out);
}

extern "C" void kernel_launch(void* const* d_in, const int* in_sizes, int n_in,
                              void* d_out, int out_size)
{
    const float4* upd4 = (const float4*)d_in[0];
    const int4*   msk4 = (const int4*)d_in[1];
    float*        out  = (float*)d_out;

    unpool_kernel<<<BLOCKS, THREADS>>>(upd4, msk4, out);
}

// round 6
// speedup vs baseline: 1.1606x; 1.1576x over previous
#include <cuda_runtime.h>
#include <cstdint>

// MaxUnpooling2D: B=16, H=128, W=128, C=64, S=2 -> out (16, 256, 256, 64)
// Each (h,w,c) scatters into its OWN 2x2 window at channel c (unique owner
// per output cell) -> one-pass window write, no atomics, no memset.
//
// R6: R1 structure (1 float4/thread, max occupancy, full 14-wave launch —
// R4 proved persistent/single-wave loses). Loads via __ldcg (skip L1
// allocate: zero reuse), stores via __stcs (evict-first). 512-thr blocks.

static constexpr int B = 16;
static constexpr int H = 128;
static constexpr int W = 128;
static constexpr int C = 64;
static constexpr int Wo = 256;   // W*2

__global__ __launch_bounds__(512) void unpool_kernel(
    const float4* __restrict__ upd4,
    const int4* __restrict__ msk4,
    float* __restrict__ out)
{
    int tid = blockIdx.x * blockDim.x + threadIdx.x;   // one thread = 4 channels
    // tid layout: [ b*H + h ][ w ][ c4 ], c4 in [0,16)
    int c4 = tid & 15;
    int w  = (tid >> 4) & (W - 1);
    int hb = tid >> 11;            // b*H + h

    float4 u = __ldcg(&upd4[tid]);
    int4   m = __ldcg(&msk4[tid]);

    float4 v0 = {0.f, 0.f, 0.f, 0.f};
    float4 v1 = v0, v2 = v0, v3 = v0;

    // t = mask >> 6 (= y*Wo + x); dx = t & 1; dy = (t >> 8) & 1; q = dy*2+dx
#define PLACE(comp)                                                   \
    {                                                                 \
        int t = m.comp >> 6;                                          \
        int q = ((t >> 7) & 2) | (t & 1);                             \
        v0.comp = (q == 0) ? u.comp : 0.f;                            \
        v1.comp = (q == 1) ? u.comp : 0.f;                            \
        v2.comp = (q == 2) ? u.comp : 0.f;                            \
        v3.comp = (q == 3) ? u.comp : 0.f;                            \
    }
    PLACE(x) PLACE(y) PLACE(z) PLACE(w)
#undef PLACE

    // output base: (2*hb*Wo + 2*w) * C + c4*4
    int base = ((hb * Wo + w) << 1) * C + (c4 << 2);

    __stcs(reinterpret_cast<float4*>(out + base),              v0); // (2h,  2w  )
    __stcs(reinterpret_cast<float4*>(out + base + C),          v1); // (2h,  2w+1)
    __stcs(reinterpret_cast<float4*>(out + base + Wo * C),     v2); // (2h+1,2w  )
    __stcs(reinterpret_cast<float4*>(out + base + Wo * C + C), v3); // (2h+1,2w+1)
}

extern "C" void kernel_launch(void* const* d_in, const int* in_sizes, int n_in,
                              void* d_out, int out_size)
{
    const float4* upd4 = (const float4*)d_in[0];
    const int4*   msk4 = (const int4*)d_in[1];
    float*        out  = (float*)d_out;

    int n4 = (B * H * W * C) / 4;            // 4,194,304 threads
    int threads = 512;
    int blocks = n4 / threads;               // 8192
    unpool_kernel<<<blocks, threads>>>(upd4, msk4, out);
}

// round 7
// speedup vs baseline: 1.1653x; 1.0040x over previous
#include <cuda_runtime.h>
#include <cstdint>

// MaxUnpooling2D: B=16, H=128, W=128, C=64, S=2 -> out (16, 256, 256, 64)
// Each (h,w,c) scatters into its OWN 2x2 window at channel c (unique owner
// per output cell) -> one-pass window write, no atomics, no memset.
//
// FINAL (R7): R1 structure — 1 float4-element/thread, 256-thr blocks,
// 16384 blocks, 22 regs, occ ~78% — plus __ldcg on the zero-reuse loads.
// Kernel is pinned at the HBM RW-mix ceiling (~6.3 TB/s effective, 79% of
// spec): traffic is minimal (134 MB reads + 268 MB writes, all full lines),
// and five independent structural levers all landed within ±0.3% of this.

static constexpr int B = 16;
static constexpr int H = 128;
static constexpr int W = 128;
static constexpr int C = 64;
static constexpr int Wo = 256;   // W*2

__global__ __launch_bounds__(256) void unpool_kernel(
    const float4* __restrict__ upd4,
    const int4* __restrict__ msk4,
    float* __restrict__ out)
{
    int tid = blockIdx.x * blockDim.x + threadIdx.x;   // one thread = 4 channels
    // tid layout: [ b*H + h ][ w ][ c4 ], c4 in [0,16)
    int c4 = tid & 15;
    int w  = (tid >> 4) & (W - 1);
    int hb = tid >> 11;            // b*H + h

    float4 u = __ldcg(&upd4[tid]);
    int4   m = __ldcg(&msk4[tid]);

    float4 v0 = {0.f, 0.f, 0.f, 0.f};
    float4 v1 = v0, v2 = v0, v3 = v0;

    // t = mask >> 6 (= y*Wo + x); dx = t & 1; dy = (t >> 8) & 1; q = dy*2+dx
#define PLACE(comp)                                                   \
    {                                                                 \
        int t = m.comp >> 6;                                          \
        int q = ((t >> 7) & 2) | (t & 1);                             \
        v0.comp = (q == 0) ? u.comp : 0.f;                            \
        v1.comp = (q == 1) ? u.comp : 0.f;                            \
        v2.comp = (q == 2) ? u.comp : 0.f;                            \
        v3.comp = (q == 3) ? u.comp : 0.f;                            \
    }
    PLACE(x) PLACE(y) PLACE(z) PLACE(w)
#undef PLACE

    // output base: (2*hb*Wo + 2*w) * C + c4*4
    int base = ((hb * Wo + w) << 1) * C + (c4 << 2);

    *reinterpret_cast<float4*>(out + base)              = v0; // (2h,  2w  )
    *reinterpret_cast<float4*>(out + base + C)          = v1; // (2h,  2w+1)
    *reinterpret_cast<float4*>(out + base + Wo * C)     = v2; // (2h+1,2w  )
    *reinterpret_cast<float4*>(out + base + Wo * C + C) = v3; // (2h+1,2w+1)
}

extern "C" void kernel_launch(void* const* d_in, const int* in_sizes, int n_in,
                              void* d_out, int out_size)
{
    const float4* upd4 = (const float4*)d_in[0];
    const int4*   msk4 = (const int4*)d_in[1];
    float*        out  = (float*)d_out;

    int n4 = (B * H * W * C) / 4;            // 4,194,304 threads
    int threads = 256;
    int blocks = n4 / threads;               // 16384
    unpool_kernel<<<blocks, threads>>>(upd4, msk4, out);
}